// round 8
// baseline (speedup 1.0000x reference)
#include <cuda_runtime.h>
#include <cuda_bf16.h>
#include <cstdint>
#include <math.h>

#define B_ 16
#define T_ 1024
#define D_ 1024
#define TD (T_ * D_)

typedef __nv_bfloat16 bf16;

// ---------------- scratch (device globals; no allocations) ----------------
static __device__ bf16 g_Xhi[B_ * TD], g_Xlo[B_ * TD];
static __device__ bf16 g_WThi[3 * D_ * D_], g_WTlo[3 * D_ * D_];
static __device__ bf16 g_W2hi[TD], g_W2lo[TD];
static __device__ bf16 g_Qhi[B_ * TD], g_Qlo[B_ * TD];
static __device__ bf16 g_Khi[B_ * TD], g_Klo[B_ * TD];
static __device__ bf16 g_Vhi[B_ * TD], g_Vlo[B_ * TD];
static __device__ float g_S[(size_t)B_ * T_ * T_];
static __device__ float g_part[B_ * 64];

// ---------------- low-level helpers ----------------
__device__ __forceinline__ uint32_t smem_u32(const void* p) {
    uint32_t a;
    asm("{ .reg .u64 t; cvta.to.shared.u64 t, %1; cvt.u32.u64 %0, t; }"
        : "=r"(a) : "l"(p));
    return a;
}
__device__ __forceinline__ void cpa16(uint32_t s, const void* g) {
    asm volatile("cp.async.cg.shared.global [%0], [%1], 16;" :: "r"(s), "l"(g));
}
__device__ __forceinline__ void cpa_commit() {
    asm volatile("cp.async.commit_group;" ::: "memory");
}
__device__ __forceinline__ void cpa_wait1() {
    asm volatile("cp.async.wait_group 1;" ::: "memory");
}
__device__ __forceinline__ void cpa_wait0() {
    asm volatile("cp.async.wait_group 0;" ::: "memory");
}
__device__ __forceinline__ void ldsm4(uint32_t (&r)[4], uint32_t addr) {
    asm volatile("ldmatrix.sync.aligned.m8n8.x4.shared.b16 {%0,%1,%2,%3}, [%4];"
        : "=r"(r[0]), "=r"(r[1]), "=r"(r[2]), "=r"(r[3]) : "r"(addr));
}
__device__ __forceinline__ void mma16816(float* d, const uint32_t* a,
                                         uint32_t b0, uint32_t b1) {
    asm volatile(
        "mma.sync.aligned.m16n8k16.row.col.f32.bf16.bf16.f32 "
        "{%0,%1,%2,%3}, {%4,%5,%6,%7}, {%8,%9}, {%0,%1,%2,%3};"
        : "+f"(d[0]), "+f"(d[1]), "+f"(d[2]), "+f"(d[3])
        : "r"(a[0]), "r"(a[1]), "r"(a[2]), "r"(a[3]), "r"(b0), "r"(b1));
}
__device__ __forceinline__ unsigned short bfbits(bf16 h) {
    return *reinterpret_cast<unsigned short*>(&h);
}

// ---------------- conversion kernels ----------------
__global__ void split_x_kernel(const float* __restrict__ in, int n4) {
    int i = blockIdx.x * blockDim.x + threadIdx.x;
    if (i >= n4) return;
    float4 v = ((const float4*)in)[i];
    float vs[4] = {v.x, v.y, v.z, v.w};
    unsigned short hb[4], lb[4];
#pragma unroll
    for (int j = 0; j < 4; j++) {
        bf16 h = __float2bfloat16(vs[j]);
        bf16 l = __float2bfloat16(vs[j] - __bfloat162float(h));
        hb[j] = bfbits(h); lb[j] = bfbits(l);
    }
    ((ushort4*)g_Xhi)[i] = make_ushort4(hb[0], hb[1], hb[2], hb[3]);
    ((ushort4*)g_Xlo)[i] = make_ushort4(lb[0], lb[1], lb[2], lb[3]);
}

__global__ void split_w2_kernel(const float* __restrict__ in, int n4) {
    int i = blockIdx.x * blockDim.x + threadIdx.x;
    if (i >= n4) return;
    float4 v = ((const float4*)in)[i];
    float vs[4] = {v.x, v.y, v.z, v.w};
    unsigned short hb[4], lb[4];
#pragma unroll
    for (int j = 0; j < 4; j++) {
        bf16 h = __float2bfloat16(vs[j]);
        bf16 l = __float2bfloat16(vs[j] - __bfloat162float(h));
        hb[j] = bfbits(h); lb[j] = bfbits(l);
    }
    ((ushort4*)g_W2hi)[i] = make_ushort4(hb[0], hb[1], hb[2], hb[3]);
    ((ushort4*)g_W2lo)[i] = make_ushort4(lb[0], lb[1], lb[2], lb[3]);
}

// Transposed split: WT[e][d] = W[d][e]
__global__ void wt_kernel(const float* __restrict__ W, int sel) {
    __shared__ float t[32][33];
    int bx = blockIdx.x, by = blockIdx.y;
    int tx = threadIdx.x, ty0 = threadIdx.y;  // 32 x 8
#pragma unroll
    for (int j = 0; j < 4; j++) {
        int r = ty0 + j * 8;
        t[r][tx] = W[(size_t)(by * 32 + r) * D_ + bx * 32 + tx];
    }
    __syncthreads();
    bf16* __restrict__ Hi = g_WThi + (size_t)sel * D_ * D_;
    bf16* __restrict__ Lo = g_WTlo + (size_t)sel * D_ * D_;
#pragma unroll
    for (int j = 0; j < 4; j++) {
        int r = ty0 + j * 8;
        float v = t[tx][r];
        bf16 h = __float2bfloat16(v);
        bf16 l = __float2bfloat16(v - __bfloat162float(h));
        size_t o = (size_t)(bx * 32 + r) * D_ + by * 32 + tx;
        Hi[o] = h; Lo[o] = l;
    }
}

// ---------------- mma.sync GEMM mainloop ----------------
// CTA tile 128x128, 4 warps (2x2), warp tile 64x64, k-tile 32, 2-stage cp.async.
// NT: C[m][n] = sum_k A[m][k]*B[n][k]. 3-pass hi/lo bf16 emulation, fp32 acc.
// 64x64 warp tiles halve SMEM read traffic vs 64x32 (each byte read by 2 warps).
#define LDB 80          // padded bytes per 64B row -> conflict-free ldmatrix
#define OPB (128 * LDB) // 10240 bytes per operand per stage
#define STAGE (4 * OPB) // 40960
#define DYN_BYTES (2 * STAGE)
#define NTHR 128

__device__ __forceinline__ void load_stage(uint32_t sb,
        const bf16* __restrict__ Ahi, const bf16* __restrict__ Alo,
        const bf16* __restrict__ Bhi, const bf16* __restrict__ Blo,
        int rowBase, int colBase, int kt, int tid) {
    const bf16* srcs[4] = {Ahi, Alo, Bhi, Blo};
#pragma unroll
    for (int op = 0; op < 4; op++) {
        int rb = (op < 2) ? rowBase : colBase;
        const bf16* s = srcs[op];
#pragma unroll
        for (int i = 0; i < 4; i++) {
            int chunk = tid + i * NTHR;  // 0..511
            int row = chunk >> 2, c = chunk & 3;
            cpa16(sb + op * OPB + row * LDB + c * 16,
                  s + (size_t)(rb + row) * D_ + kt * 32 + c * 8);
        }
    }
}

// acc[im][in][4]: im = 16-row block (4), in = 8-col block (8)
__device__ __forceinline__ void gemm_ml(uint32_t sbase,
        const bf16* __restrict__ Ahi, const bf16* __restrict__ Alo,
        const bf16* __restrict__ Bhi, const bf16* __restrict__ Blo,
        int rowBase, int colBase, int tid, float acc[4][8][4]) {
    const int lane = tid & 31, wid = tid >> 5;
    const int wm = wid & 1, wn = wid >> 1;   // 2x2 warps
    const int lrow = lane & 15;
    const int lcol = (lane >> 4) * 16;

#pragma unroll
    for (int im = 0; im < 4; im++)
#pragma unroll
        for (int in = 0; in < 8; in++)
#pragma unroll
            for (int j = 0; j < 4; j++) acc[im][in][j] = 0.f;

    load_stage(sbase, Ahi, Alo, Bhi, Blo, rowBase, colBase, 0, tid);
    cpa_commit();

    for (int kt = 0; kt < 32; kt++) {
        if (kt + 1 < 32) {
            load_stage(sbase + ((kt + 1) & 1) * STAGE, Ahi, Alo, Bhi, Blo,
                       rowBase, colBase, kt + 1, tid);
            cpa_commit();
            cpa_wait1();
        } else {
            cpa_wait0();
        }
        __syncthreads();

        uint32_t st = sbase + (kt & 1) * STAGE;
        uint32_t aA = st + (wm * 64 + lrow) * LDB + lcol;
        uint32_t aB = st + 2 * OPB + (wn * 64 + lrow) * LDB + lcol;
#pragma unroll
        for (int kk = 0; kk < 2; kk++) {
            // B fragments for this k-half: 64 cols hi+lo = 32 regs
            uint32_t bh[4][4], bl[4][4];
#pragma unroll
            for (int g = 0; g < 4; g++) {
                ldsm4(bh[g], aB + g * 16 * LDB + kk * 32);
                ldsm4(bl[g], aB + OPB + g * 16 * LDB + kk * 32);
            }
            // A fragments per-im (register-lean)
#pragma unroll
            for (int im = 0; im < 4; im++) {
                uint32_t ah[4], al[4];
                ldsm4(ah, aA + im * 16 * LDB + kk * 32);
                ldsm4(al, aA + OPB + im * 16 * LDB + kk * 32);
#pragma unroll
                for (int g = 0; g < 4; g++) {
                    mma16816(acc[im][g * 2 + 0], ah, bh[g][0], bh[g][2]);
                    mma16816(acc[im][g * 2 + 1], ah, bh[g][1], bh[g][3]);
                }
#pragma unroll
                for (int g = 0; g < 4; g++) {
                    mma16816(acc[im][g * 2 + 0], ah, bl[g][0], bl[g][2]);
                    mma16816(acc[im][g * 2 + 1], ah, bl[g][1], bl[g][3]);
                }
#pragma unroll
                for (int g = 0; g < 4; g++) {
                    mma16816(acc[im][g * 2 + 0], al, bh[g][0], bh[g][2]);
                    mma16816(acc[im][g * 2 + 1], al, bh[g][1], bh[g][3]);
                }
            }
        }
        __syncthreads();
    }
}

// ---------------- proj: O = X @ WT (+bias) * scale, split to bf16 hi/lo ----
__global__ void __launch_bounds__(NTHR, 2)
proj_mma(const float* __restrict__ bias, int sel, float scale) {
    extern __shared__ char dyn[];
    uint32_t sbase = smem_u32(dyn);
    const int tid = threadIdx.x;
    const int lane = tid & 31, wid = tid >> 5;
    const int wm = wid & 1, wn = wid >> 1;
    const int rowBase = blockIdx.y * 128, colBase = blockIdx.x * 128;

    const bf16* WThi = g_WThi + (size_t)sel * D_ * D_;
    const bf16* WTlo = g_WTlo + (size_t)sel * D_ * D_;
    bf16* Ohi = (sel == 0) ? g_Qhi : (sel == 1) ? g_Khi : g_Vhi;
    bf16* Olo = (sel == 0) ? g_Qlo : (sel == 1) ? g_Klo : g_Vlo;

    float acc[4][8][4];
    gemm_ml(sbase, g_Xhi, g_Xlo, WThi, WTlo, rowBase, colBase, tid, acc);

#pragma unroll
    for (int in = 0; in < 8; in++) {
        int col = colBase + wn * 64 + in * 8 + (lane & 3) * 2;
        float2 bb = *(const float2*)(bias + col);
#pragma unroll
        for (int im = 0; im < 4; im++) {
            int row0 = rowBase + wm * 64 + im * 16 + (lane >> 2);
            float v00 = (acc[im][in][0] + bb.x) * scale;
            float v01 = (acc[im][in][1] + bb.y) * scale;
            float v10 = (acc[im][in][2] + bb.x) * scale;
            float v11 = (acc[im][in][3] + bb.y) * scale;
            bf16 h00 = __float2bfloat16(v00), h01 = __float2bfloat16(v01);
            bf16 h10 = __float2bfloat16(v10), h11 = __float2bfloat16(v11);
            bf16 l00 = __float2bfloat16(v00 - __bfloat162float(h00));
            bf16 l01 = __float2bfloat16(v01 - __bfloat162float(h01));
            bf16 l10 = __float2bfloat16(v10 - __bfloat162float(h10));
            bf16 l11 = __float2bfloat16(v11 - __bfloat162float(h11));
            size_t o0 = (size_t)row0 * D_ + col;
            size_t o1 = (size_t)(row0 + 8) * D_ + col;
            *(ushort2*)(Ohi + o0) = make_ushort2(bfbits(h00), bfbits(h01));
            *(ushort2*)(Olo + o0) = make_ushort2(bfbits(l00), bfbits(l01));
            *(ushort2*)(Ohi + o1) = make_ushort2(bfbits(h10), bfbits(h11));
            *(ushort2*)(Olo + o1) = make_ushort2(bfbits(l10), bfbits(l11));
        }
    }
}

// ---------------- scores: ST[b,k,q] = K . Q^T (scale folded into Q) -------
__global__ void __launch_bounds__(NTHR, 2)
scores_mma() {
    extern __shared__ char dyn[];
    uint32_t sbase = smem_u32(dyn);
    const int tid = threadIdx.x;
    const int lane = tid & 31, wid = tid >> 5;
    const int wm = wid & 1, wn = wid >> 1;
    const int b = blockIdx.z;
    const int rowBase = blockIdx.y * 128, colBase = blockIdx.x * 128;

    float acc[4][8][4];
    gemm_ml(sbase, g_Khi + (size_t)b * TD, g_Klo + (size_t)b * TD,
            g_Qhi + (size_t)b * TD, g_Qlo + (size_t)b * TD,
            rowBase, colBase, tid, acc);

    float* __restrict__ S = g_S + (size_t)b * T_ * T_;
#pragma unroll
    for (int im = 0; im < 4; im++) {
        int row0 = rowBase + wm * 64 + im * 16 + (lane >> 2);
#pragma unroll
        for (int in = 0; in < 8; in++) {
            int col = colBase + wn * 64 + in * 8 + (lane & 3) * 2;
            *(float2*)(S + (size_t)row0 * T_ + col) =
                make_float2(acc[im][in][0], acc[im][in][1]);
            *(float2*)(S + (size_t)(row0 + 8) * T_ + col) =
                make_float2(acc[im][in][2], acc[im][in][3]);
        }
    }
}

// ---------------- softmax over rows of ST (fp32) --------------------------
__global__ void softmax_kernel() {
    const int warp = threadIdx.x >> 5, lane = threadIdx.x & 31;
    const size_t row = (size_t)blockIdx.x * 8 + warp;
    float* p = g_S + row * T_;
    float4 v[8];
#pragma unroll
    for (int i = 0; i < 8; i++) v[i] = *(const float4*)(p + (lane + 32 * i) * 4);
    float m = -3.4e38f;
#pragma unroll
    for (int i = 0; i < 8; i++)
        m = fmaxf(m, fmaxf(fmaxf(v[i].x, v[i].y), fmaxf(v[i].z, v[i].w)));
#pragma unroll
    for (int o = 16; o; o >>= 1) m = fmaxf(m, __shfl_xor_sync(0xffffffffu, m, o));
    float s = 0.f;
#pragma unroll
    for (int i = 0; i < 8; i++) {
        v[i].x = expf(v[i].x - m); v[i].y = expf(v[i].y - m);
        v[i].z = expf(v[i].z - m); v[i].w = expf(v[i].w - m);
        s += v[i].x + v[i].y + v[i].z + v[i].w;
    }
#pragma unroll
    for (int o = 16; o; o >>= 1) s += __shfl_xor_sync(0xffffffffu, s, o);
    const float inv = 1.0f / s;
#pragma unroll
    for (int i = 0; i < 8; i++) {
        v[i].x *= inv; v[i].y *= inv; v[i].z *= inv; v[i].w *= inv;
        *(float4*)(p + (lane + 32 * i) * 4) = v[i];
    }
}

// ---------------- dot: sum over tile of (V.W2^T)[k,q] * attnT[b,k,q] ------
__global__ void __launch_bounds__(NTHR, 2)
dot_mma() {
    extern __shared__ char dyn[];
    __shared__ float red[NTHR];
    uint32_t sbase = smem_u32(dyn);
    const int tid = threadIdx.x;
    const int lane = tid & 31, wid = tid >> 5;
    const int wm = wid & 1, wn = wid >> 1;
    const int b = blockIdx.z;
    const int rowBase = blockIdx.y * 128, colBase = blockIdx.x * 128;

    float acc[4][8][4];
    gemm_ml(sbase, g_Vhi + (size_t)b * TD, g_Vlo + (size_t)b * TD,
            g_W2hi, g_W2lo, rowBase, colBase, tid, acc);

    const float* __restrict__ S = g_S + (size_t)b * T_ * T_;
    float lsum = 0.f;
#pragma unroll
    for (int im = 0; im < 4; im++) {
        int row0 = rowBase + wm * 64 + im * 16 + (lane >> 2);
#pragma unroll
        for (int in = 0; in < 8; in++) {
            int col = colBase + wn * 64 + in * 8 + (lane & 3) * 2;
            float2 s0 = *(const float2*)(S + (size_t)row0 * T_ + col);
            float2 s1 = *(const float2*)(S + (size_t)(row0 + 8) * T_ + col);
            lsum += acc[im][in][0] * s0.x + acc[im][in][1] * s0.y
                  + acc[im][in][2] * s1.x + acc[im][in][3] * s1.y;
        }
    }
    red[tid] = lsum;
    __syncthreads();
#pragma unroll
    for (int s = NTHR / 2; s > 0; s >>= 1) {
        if (tid < s) red[tid] += red[tid + s];
        __syncthreads();
    }
    if (tid == 0) g_part[b * 64 + blockIdx.y * 8 + blockIdx.x] = red[0];
}

__global__ void final_kernel(const float* __restrict__ bfc, float* __restrict__ out) {
    const int b = blockIdx.x;
    const int tid = threadIdx.x;  // 64
    float v = g_part[b * 64 + tid];
#pragma unroll
    for (int o = 16; o; o >>= 1) v += __shfl_xor_sync(0xffffffffu, v, o);
    __shared__ float sh[2];
    if ((tid & 31) == 0) sh[tid >> 5] = v;
    __syncthreads();
    if (tid == 0) out[b] = sh[0] + sh[1] + bfc[0];
}

// ---------------- launch ----------------
extern "C" void kernel_launch(void* const* d_in, const int* in_sizes, int n_in,
                              void* d_out, int out_size) {
    (void)in_sizes; (void)n_in; (void)out_size;
    const float* x   = (const float*)d_in[0];
    const float* Wq  = (const float*)d_in[1];
    const float* bq  = (const float*)d_in[2];
    const float* Wk  = (const float*)d_in[3];
    const float* bk  = (const float*)d_in[4];
    const float* Wv  = (const float*)d_in[5];
    const float* bv  = (const float*)d_in[6];
    const float* Wfc = (const float*)d_in[7];
    const float* bfc = (const float*)d_in[8];
    float* out = (float*)d_out;

    cudaFuncSetAttribute(proj_mma,   cudaFuncAttributeMaxDynamicSharedMemorySize, DYN_BYTES);
    cudaFuncSetAttribute(scores_mma, cudaFuncAttributeMaxDynamicSharedMemorySize, DYN_BYTES);
    cudaFuncSetAttribute(dot_mma,    cudaFuncAttributeMaxDynamicSharedMemorySize, DYN_BYTES);

    split_x_kernel<<<(B_ * TD / 4 + 255) / 256, 256>>>(x, B_ * TD / 4);
    dim3 wtg(32, 32), wtb(32, 8);
    wt_kernel<<<wtg, wtb>>>(Wq, 0);
    wt_kernel<<<wtg, wtb>>>(Wk, 1);
    wt_kernel<<<wtg, wtb>>>(Wv, 2);
    split_w2_kernel<<<(TD / 4 + 255) / 256, 256>>>(Wfc, TD / 4);

    dim3 gp(8, 128);
    proj_mma<<<gp, NTHR, DYN_BYTES>>>(bq, 0, 0.03125f);  // 1/sqrt(D) folded into Q
    proj_mma<<<gp, NTHR, DYN_BYTES>>>(bk, 1, 1.0f);
    proj_mma<<<gp, NTHR, DYN_BYTES>>>(bv, 2, 1.0f);

    dim3 gs(8, 8, B_);
    scores_mma<<<gs, NTHR, DYN_BYTES>>>();
    softmax_kernel<<<(B_ * T_) / 8, 256>>>();
    dot_mma<<<gs, NTHR, DYN_BYTES>>>();
    final_kernel<<<B_, 64>>>(bfc, out);
}

// round 9
// speedup vs baseline: 1.4784x; 1.4784x over previous
#include <cuda_runtime.h>
#include <cuda_bf16.h>
#include <cstdint>
#include <math.h>

#define B_ 16
#define T_ 1024
#define D_ 1024
#define TD (T_ * D_)

typedef __nv_bfloat16 bf16;

// ---------------- scratch (device globals; no allocations) ----------------
static __device__ bf16 g_Xhi[B_ * TD], g_Xlo[B_ * TD];
static __device__ bf16 g_Wqhi[D_ * D_], g_Wqlo[D_ * D_];
static __device__ bf16 g_Wkhi[D_ * D_], g_Wklo[D_ * D_];
static __device__ bf16 g_Wvhi[D_ * D_], g_Wvlo[D_ * D_];
static __device__ bf16 g_W2hi[TD], g_W2lo[TD];
static __device__ bf16 g_N1hi[D_ * D_], g_N1lo[D_ * D_];   // N1[d',d] = (1/32)*sum_e Wq[d',e]Wk[d,e]
static __device__ bf16 g_N2hi[T_ * D_], g_N2lo[T_ * D_];   // N2[q,d]  = sum_e W2[q,e]Wv[d,e]
static __device__ bf16 g_Yhi[B_ * TD], g_Ylo[B_ * TD];     // Y = X * M * (1/32)
static __device__ float g_S[(size_t)B_ * T_ * T_];
static __device__ float g_u[D_];       // (1/32) * Wq . bk
static __device__ float g_c[B_ * T_];  // x_t . u
static __device__ float g_r2[T_];      // bv . W2[q]
static __device__ float g_part[B_ * 64];

// ---------------- low-level helpers ----------------
__device__ __forceinline__ uint32_t smem_u32(const void* p) {
    uint32_t a;
    asm("{ .reg .u64 t; cvta.to.shared.u64 t, %1; cvt.u32.u64 %0, t; }"
        : "=r"(a) : "l"(p));
    return a;
}
__device__ __forceinline__ void cpa16(uint32_t s, const void* g) {
    asm volatile("cp.async.cg.shared.global [%0], [%1], 16;" :: "r"(s), "l"(g));
}
__device__ __forceinline__ void cpa_commit() {
    asm volatile("cp.async.commit_group;" ::: "memory");
}
__device__ __forceinline__ void cpa_wait1() {
    asm volatile("cp.async.wait_group 1;" ::: "memory");
}
__device__ __forceinline__ void cpa_wait0() {
    asm volatile("cp.async.wait_group 0;" ::: "memory");
}
__device__ __forceinline__ void ldsm4(uint32_t (&r)[4], uint32_t addr) {
    asm volatile("ldmatrix.sync.aligned.m8n8.x4.shared.b16 {%0,%1,%2,%3}, [%4];"
        : "=r"(r[0]), "=r"(r[1]), "=r"(r[2]), "=r"(r[3]) : "r"(addr));
}
__device__ __forceinline__ void mma16816(float* d, const uint32_t* a,
                                         uint32_t b0, uint32_t b1) {
    asm volatile(
        "mma.sync.aligned.m16n8k16.row.col.f32.bf16.bf16.f32 "
        "{%0,%1,%2,%3}, {%4,%5,%6,%7}, {%8,%9}, {%0,%1,%2,%3};"
        : "+f"(d[0]), "+f"(d[1]), "+f"(d[2]), "+f"(d[3])
        : "r"(a[0]), "r"(a[1]), "r"(a[2]), "r"(a[3]), "r"(b0), "r"(b1));
}
__device__ __forceinline__ unsigned short bfbits(bf16 h) {
    return *reinterpret_cast<unsigned short*>(&h);
}

// ---------------- split kernel (fp32 -> bf16 hi/lo), selector dest --------
__device__ __forceinline__ void get_split_dst(int sel, bf16*& hi, bf16*& lo) {
    switch (sel) {
        case 0: hi = g_Xhi;  lo = g_Xlo;  break;
        case 1: hi = g_Wqhi; lo = g_Wqlo; break;
        case 2: hi = g_Wkhi; lo = g_Wklo; break;
        case 3: hi = g_Wvhi; lo = g_Wvlo; break;
        default: hi = g_W2hi; lo = g_W2lo; break;
    }
}

__global__ void split_kernel(const float* __restrict__ in, int sel, int n4) {
    int i = blockIdx.x * blockDim.x + threadIdx.x;
    if (i >= n4) return;
    bf16 *hi, *lo;
    get_split_dst(sel, hi, lo);
    float4 v = ((const float4*)in)[i];
    float vs[4] = {v.x, v.y, v.z, v.w};
    unsigned short hb[4], lb[4];
#pragma unroll
    for (int j = 0; j < 4; j++) {
        bf16 h = __float2bfloat16(vs[j]);
        bf16 l = __float2bfloat16(vs[j] - __bfloat162float(h));
        hb[j] = bfbits(h); lb[j] = bfbits(l);
    }
    ((ushort4*)hi)[i] = make_ushort4(hb[0], hb[1], hb[2], hb[3]);
    ((ushort4*)lo)[i] = make_ushort4(lb[0], lb[1], lb[2], lb[3]);
}

// ---------------- GEMV kernels (warp per row, fp32) ----------------
__global__ void gemv_u(const float* __restrict__ Wq, const float* __restrict__ bk) {
    int warp = threadIdx.x >> 5, lane = threadIdx.x & 31;
    int row = blockIdx.x * 8 + warp;
    const float4* w4 = (const float4*)(Wq + (size_t)row * D_);
    const float4* b4 = (const float4*)bk;
    float s = 0.f;
#pragma unroll
    for (int i = 0; i < 8; i++) {
        float4 w = w4[lane + i * 32], b = b4[lane + i * 32];
        s += w.x * b.x + w.y * b.y + w.z * b.z + w.w * b.w;
    }
#pragma unroll
    for (int o = 16; o; o >>= 1) s += __shfl_xor_sync(0xffffffffu, s, o);
    if (lane == 0) g_u[row] = s * 0.03125f;
}

__global__ void gemv_r2(const float* __restrict__ bv, const float* __restrict__ Wfc) {
    int warp = threadIdx.x >> 5, lane = threadIdx.x & 31;
    int q = blockIdx.x * 8 + warp;
    const float4* w4 = (const float4*)(Wfc + (size_t)q * D_);
    const float4* b4 = (const float4*)bv;
    float s = 0.f;
#pragma unroll
    for (int i = 0; i < 8; i++) {
        float4 w = w4[lane + i * 32], b = b4[lane + i * 32];
        s += w.x * b.x + w.y * b.y + w.z * b.z + w.w * b.w;
    }
#pragma unroll
    for (int o = 16; o; o >>= 1) s += __shfl_xor_sync(0xffffffffu, s, o);
    if (lane == 0) g_r2[q] = s;
}

__global__ void gemv_c(const float* __restrict__ x) {
    int warp = threadIdx.x >> 5, lane = threadIdx.x & 31;
    int row = blockIdx.x * 8 + warp;   // 0..16383
    const float4* x4 = (const float4*)(x + (size_t)row * D_);
    const float4* u4 = (const float4*)g_u;
    float s = 0.f;
#pragma unroll
    for (int i = 0; i < 8; i++) {
        float4 w = x4[lane + i * 32], b = u4[lane + i * 32];
        s += w.x * b.x + w.y * b.y + w.z * b.z + w.w * b.w;
    }
#pragma unroll
    for (int o = 16; o; o >>= 1) s += __shfl_xor_sync(0xffffffffu, s, o);
    if (lane == 0) g_c[row] = s;
}

// ---------------- mma.sync GEMM mainloop (R7 config: 8 warps, 64x32) ------
#define LDB 80          // padded bytes per 64B row -> conflict-free ldmatrix
#define OPB (128 * LDB) // 10240 bytes per operand per stage
#define STAGE (4 * OPB) // 40960
#define DYN_BYTES (2 * STAGE)

__device__ __forceinline__ void load_stage(uint32_t sb,
        const bf16* __restrict__ Ahi, const bf16* __restrict__ Alo,
        const bf16* __restrict__ Bhi, const bf16* __restrict__ Blo,
        int rowBase, int colBase, int kt, int tid) {
    const bf16* srcs[4] = {Ahi, Alo, Bhi, Blo};
#pragma unroll
    for (int op = 0; op < 4; op++) {
        int rb = (op < 2) ? rowBase : colBase;
        const bf16* s = srcs[op];
#pragma unroll
        for (int i = 0; i < 2; i++) {
            int chunk = tid + i * 256;   // 0..511
            int row = chunk >> 2, c = chunk & 3;
            cpa16(sb + op * OPB + row * LDB + c * 16,
                  s + (size_t)(rb + row) * D_ + kt * 32 + c * 8);
        }
    }
}

__device__ __forceinline__ void gemm_ml(uint32_t sbase,
        const bf16* __restrict__ Ahi, const bf16* __restrict__ Alo,
        const bf16* __restrict__ Bhi, const bf16* __restrict__ Blo,
        int rowBase, int colBase, int tid, float acc[4][4][4]) {
    const int lane = tid & 31, wid = tid >> 5;
    const int wm = wid & 1, wn = wid >> 1;
    const int lrow = lane & 15;
    const int lcol = (lane >> 4) * 16;

#pragma unroll
    for (int im = 0; im < 4; im++)
#pragma unroll
        for (int in = 0; in < 4; in++)
#pragma unroll
            for (int j = 0; j < 4; j++) acc[im][in][j] = 0.f;

    load_stage(sbase, Ahi, Alo, Bhi, Blo, rowBase, colBase, 0, tid);
    cpa_commit();

    for (int kt = 0; kt < 32; kt++) {
        if (kt + 1 < 32) {
            load_stage(sbase + ((kt + 1) & 1) * STAGE, Ahi, Alo, Bhi, Blo,
                       rowBase, colBase, kt + 1, tid);
            cpa_commit();
            cpa_wait1();
        } else {
            cpa_wait0();
        }
        __syncthreads();

        uint32_t st = sbase + (kt & 1) * STAGE;
        uint32_t aA = st + (wm * 64 + lrow) * LDB + lcol;
        uint32_t aB = st + 2 * OPB + (wn * 32 + lrow) * LDB + lcol;
#pragma unroll
        for (int kk = 0; kk < 2; kk++) {
            uint32_t bh[2][4], bl[2][4];
#pragma unroll
            for (int g = 0; g < 2; g++) {
                ldsm4(bh[g], aB + g * 16 * LDB + kk * 32);
                ldsm4(bl[g], aB + OPB + g * 16 * LDB + kk * 32);
            }
#pragma unroll
            for (int im = 0; im < 4; im++) {
                uint32_t ah[4], al[4];
                ldsm4(ah, aA + im * 16 * LDB + kk * 32);
                ldsm4(al, aA + OPB + im * 16 * LDB + kk * 32);
#pragma unroll
                for (int g = 0; g < 2; g++) {
                    mma16816(acc[im][g * 2 + 0], ah, bh[g][0], bh[g][2]);
                    mma16816(acc[im][g * 2 + 1], ah, bh[g][1], bh[g][3]);
                }
#pragma unroll
                for (int g = 0; g < 2; g++) {
                    mma16816(acc[im][g * 2 + 0], ah, bl[g][0], bl[g][2]);
                    mma16816(acc[im][g * 2 + 1], ah, bl[g][1], bl[g][3]);
                }
#pragma unroll
                for (int g = 0; g < 2; g++) {
                    mma16816(acc[im][g * 2 + 0], al, bh[g][0], bh[g][2]);
                    mma16816(acc[im][g * 2 + 1], al, bh[g][1], bh[g][3]);
                }
            }
        }
        __syncthreads();
    }
}

// ---------------- generic NT gemm -> scaled bf16 hi/lo output -------------
// job 0: N1 = Wq . Wk^T * 1/32   [1024 x 1024]
// job 1: N2 = W2 . Wv^T          [1024 x 1024]
// job 2: Y  = X  . N1^T          [16384 x 1024]
__device__ __forceinline__ void get_job(int job,
        const bf16*& Ahi, const bf16*& Alo, const bf16*& Bhi, const bf16*& Blo,
        bf16*& Ohi, bf16*& Olo, float& scale) {
    if (job == 0) {
        Ahi = g_Wqhi; Alo = g_Wqlo; Bhi = g_Wkhi; Blo = g_Wklo;
        Ohi = g_N1hi; Olo = g_N1lo; scale = 0.03125f;
    } else if (job == 1) {
        Ahi = g_W2hi; Alo = g_W2lo; Bhi = g_Wvhi; Blo = g_Wvlo;
        Ohi = g_N2hi; Olo = g_N2lo; scale = 1.0f;
    } else {
        Ahi = g_Xhi; Alo = g_Xlo; Bhi = g_N1hi; Blo = g_N1lo;
        Ohi = g_Yhi; Olo = g_Ylo; scale = 1.0f;
    }
}

__global__ void __launch_bounds__(256, 2)
gemm_split(int job) {
    extern __shared__ char dyn[];
    uint32_t sbase = smem_u32(dyn);
    const int tid = threadIdx.x;
    const int lane = tid & 31, wid = tid >> 5;
    const int wm = wid & 1, wn = wid >> 1;
    const int rowBase = blockIdx.y * 128, colBase = blockIdx.x * 128;

    const bf16 *Ahi, *Alo, *Bhi, *Blo;
    bf16 *Ohi, *Olo;
    float scale;
    get_job(job, Ahi, Alo, Bhi, Blo, Ohi, Olo, scale);

    float acc[4][4][4];
    gemm_ml(sbase, Ahi, Alo, Bhi, Blo, rowBase, colBase, tid, acc);

#pragma unroll
    for (int in = 0; in < 4; in++) {
        int col = colBase + wn * 32 + in * 8 + (lane & 3) * 2;
#pragma unroll
        for (int im = 0; im < 4; im++) {
            int row0 = rowBase + wm * 64 + im * 16 + (lane >> 2);
            float v00 = acc[im][in][0] * scale;
            float v01 = acc[im][in][1] * scale;
            float v10 = acc[im][in][2] * scale;
            float v11 = acc[im][in][3] * scale;
            bf16 h00 = __float2bfloat16(v00), h01 = __float2bfloat16(v01);
            bf16 h10 = __float2bfloat16(v10), h11 = __float2bfloat16(v11);
            bf16 l00 = __float2bfloat16(v00 - __bfloat162float(h00));
            bf16 l01 = __float2bfloat16(v01 - __bfloat162float(h01));
            bf16 l10 = __float2bfloat16(v10 - __bfloat162float(h10));
            bf16 l11 = __float2bfloat16(v11 - __bfloat162float(h11));
            size_t o0 = (size_t)row0 * D_ + col;
            size_t o1 = (size_t)(row0 + 8) * D_ + col;
            *(ushort2*)(Ohi + o0) = make_ushort2(bfbits(h00), bfbits(h01));
            *(ushort2*)(Olo + o0) = make_ushort2(bfbits(l00), bfbits(l01));
            *(ushort2*)(Ohi + o1) = make_ushort2(bfbits(h10), bfbits(h11));
            *(ushort2*)(Olo + o1) = make_ushort2(bfbits(l10), bfbits(l11));
        }
    }
}

// ---------------- scores: ST[b,k,q] = Y_b[k] . X_b[q] + c_b[q] ------------
__global__ void __launch_bounds__(256, 2)
st_mma() {
    extern __shared__ char dyn[];
    uint32_t sbase = smem_u32(dyn);
    const int tid = threadIdx.x;
    const int lane = tid & 31, wid = tid >> 5;
    const int wm = wid & 1, wn = wid >> 1;
    const int b = blockIdx.z;
    const int rowBase = blockIdx.y * 128, colBase = blockIdx.x * 128;

    float acc[4][4][4];
    gemm_ml(sbase, g_Yhi + (size_t)b * TD, g_Ylo + (size_t)b * TD,
            g_Xhi + (size_t)b * TD, g_Xlo + (size_t)b * TD,
            rowBase, colBase, tid, acc);

    float* __restrict__ S = g_S + (size_t)b * T_ * T_;
    const float* __restrict__ c = g_c + (size_t)b * T_;
#pragma unroll
    for (int in = 0; in < 4; in++) {
        int col = colBase + wn * 32 + in * 8 + (lane & 3) * 2;
        float2 cc = *(const float2*)(c + col);
#pragma unroll
        for (int im = 0; im < 4; im++) {
            int row0 = rowBase + wm * 64 + im * 16 + (lane >> 2);
            *(float2*)(S + (size_t)row0 * T_ + col) =
                make_float2(acc[im][in][0] + cc.x, acc[im][in][1] + cc.y);
            *(float2*)(S + (size_t)(row0 + 8) * T_ + col) =
                make_float2(acc[im][in][2] + cc.x, acc[im][in][3] + cc.y);
        }
    }
}

// ---------------- softmax over rows of ST (fp32) --------------------------
__global__ void softmax_kernel() {
    const int warp = threadIdx.x >> 5, lane = threadIdx.x & 31;
    const size_t row = (size_t)blockIdx.x * 8 + warp;
    float* p = g_S + row * T_;
    float4 v[8];
#pragma unroll
    for (int i = 0; i < 8; i++) v[i] = *(const float4*)(p + (lane + 32 * i) * 4);
    float m = -3.4e38f;
#pragma unroll
    for (int i = 0; i < 8; i++)
        m = fmaxf(m, fmaxf(fmaxf(v[i].x, v[i].y), fmaxf(v[i].z, v[i].w)));
#pragma unroll
    for (int o = 16; o; o >>= 1) m = fmaxf(m, __shfl_xor_sync(0xffffffffu, m, o));
    float s = 0.f;
#pragma unroll
    for (int i = 0; i < 8; i++) {
        v[i].x = expf(v[i].x - m); v[i].y = expf(v[i].y - m);
        v[i].z = expf(v[i].z - m); v[i].w = expf(v[i].w - m);
        s += v[i].x + v[i].y + v[i].z + v[i].w;
    }
#pragma unroll
    for (int o = 16; o; o >>= 1) s += __shfl_xor_sync(0xffffffffu, s, o);
    const float inv = 1.0f / s;
#pragma unroll
    for (int i = 0; i < 8; i++) {
        v[i].x *= inv; v[i].y *= inv; v[i].z *= inv; v[i].w *= inv;
        *(float4*)(p + (lane + 32 * i) * 4) = v[i];
    }
}

// ---------------- dot: sum (X_b . N2^T + r2[q]) * attnT[b,k,q] ------------
__global__ void __launch_bounds__(256, 2)
dot_mma() {
    extern __shared__ char dyn[];
    __shared__ float red[256];
    uint32_t sbase = smem_u32(dyn);
    const int tid = threadIdx.x;
    const int lane = tid & 31, wid = tid >> 5;
    const int wm = wid & 1, wn = wid >> 1;
    const int b = blockIdx.z;
    const int rowBase = blockIdx.y * 128, colBase = blockIdx.x * 128;

    float acc[4][4][4];
    gemm_ml(sbase, g_Xhi + (size_t)b * TD, g_Xlo + (size_t)b * TD,
            g_N2hi, g_N2lo, rowBase, colBase, tid, acc);

    const float* __restrict__ S = g_S + (size_t)b * T_ * T_;
    float lsum = 0.f;
#pragma unroll
    for (int in = 0; in < 4; in++) {
        int col = colBase + wn * 32 + in * 8 + (lane & 3) * 2;
        float2 rr = *(const float2*)(g_r2 + col);
#pragma unroll
        for (int im = 0; im < 4; im++) {
            int row0 = rowBase + wm * 64 + im * 16 + (lane >> 2);
            float2 s0 = *(const float2*)(S + (size_t)row0 * T_ + col);
            float2 s1 = *(const float2*)(S + (size_t)(row0 + 8) * T_ + col);
            lsum += (acc[im][in][0] + rr.x) * s0.x + (acc[im][in][1] + rr.y) * s0.y
                  + (acc[im][in][2] + rr.x) * s1.x + (acc[im][in][3] + rr.y) * s1.y;
        }
    }
    red[tid] = lsum;
    __syncthreads();
#pragma unroll
    for (int s = 128; s > 0; s >>= 1) {
        if (tid < s) red[tid] += red[tid + s];
        __syncthreads();
    }
    if (tid == 0) g_part[b * 64 + blockIdx.y * 8 + blockIdx.x] = red[0];
}

__global__ void final_kernel(const float* __restrict__ bfc, float* __restrict__ out) {
    const int b = blockIdx.x;
    const int tid = threadIdx.x;  // 64
    float v = g_part[b * 64 + tid];
#pragma unroll
    for (int o = 16; o; o >>= 1) v += __shfl_xor_sync(0xffffffffu, v, o);
    __shared__ float sh[2];
    if ((tid & 31) == 0) sh[tid >> 5] = v;
    __syncthreads();
    if (tid == 0) out[b] = sh[0] + sh[1] + bfc[0];
}

// ---------------- launch ----------------
extern "C" void kernel_launch(void* const* d_in, const int* in_sizes, int n_in,
                              void* d_out, int out_size) {
    (void)in_sizes; (void)n_in; (void)out_size;
    const float* x   = (const float*)d_in[0];
    const float* Wq  = (const float*)d_in[1];
    const float* bk  = (const float*)d_in[4];
    const float* Wk  = (const float*)d_in[3];
    const float* Wv  = (const float*)d_in[5];
    const float* bv  = (const float*)d_in[6];
    const float* Wfc = (const float*)d_in[7];
    const float* bfc = (const float*)d_in[8];
    float* out = (float*)d_out;

    cudaFuncSetAttribute(gemm_split, cudaFuncAttributeMaxDynamicSharedMemorySize, DYN_BYTES);
    cudaFuncSetAttribute(st_mma,     cudaFuncAttributeMaxDynamicSharedMemorySize, DYN_BYTES);
    cudaFuncSetAttribute(dot_mma,    cudaFuncAttributeMaxDynamicSharedMemorySize, DYN_BYTES);

    // splits
    split_kernel<<<B_ * TD / 4 / 256, 256>>>(x, 0, B_ * TD / 4);
    split_kernel<<<D_ * D_ / 4 / 256, 256>>>(Wq, 1, D_ * D_ / 4);
    split_kernel<<<D_ * D_ / 4 / 256, 256>>>(Wk, 2, D_ * D_ / 4);
    split_kernel<<<D_ * D_ / 4 / 256, 256>>>(Wv, 3, D_ * D_ / 4);
    split_kernel<<<TD / 4 / 256, 256>>>(Wfc, 4, TD / 4);

    // GEMVs (bias terms)
    gemv_u<<<D_ / 8, 256>>>(Wq, bk);
    gemv_r2<<<T_ / 8, 256>>>(bv, Wfc);
    gemv_c<<<B_ * T_ / 8, 256>>>(x);

    // weight-weight folds + Y
    gemm_split<<<dim3(8, 8), 256, DYN_BYTES>>>(0);        // N1
    gemm_split<<<dim3(8, 8), 256, DYN_BYTES>>>(1);        // N2
    gemm_split<<<dim3(8, 128), 256, DYN_BYTES>>>(2);      // Y

    // scores + softmax + fused output
    dim3 gs(8, 8, B_);
    st_mma<<<gs, 256, DYN_BYTES>>>();
    softmax_kernel<<<(B_ * T_) / 8, 256>>>();
    dot_mma<<<gs, 256, DYN_BYTES>>>();
    final_kernel<<<B_, 64>>>(bfc, out);
}